// round 5
// baseline (speedup 1.0000x reference)
#include <cuda_runtime.h>
#include <cuda_fp16.h>
#include <cstdint>

#define NN     2048
#define NODES  4096
#define GRID   512                    // must be co-resident (4 CTAs/SM on 148 SMs)
#define TPB    256
#define LOG2E  1.4426950408889634f

// ---------------- device scratch ----------------
__device__ __align__(16) __half g_d[(size_t)NODES * NN];  // (F1-F0)*log2e fp16, 16.8MB
__device__ __align__(16) float  g_s1[2][NODES];           // s1 ping-pong
__device__ __align__(16) float  g_A[NODES];               // row sums
__device__ __align__(16) float  g_Bv[NODES];              // reduced column sums
__device__ __align__(16) float  g_BvP[GRID][NN];          // per-block column partials (4MB)
__device__ unsigned g_bar[16];                            // spin-barrier counters

__device__ __forceinline__ float ex2f(float x) {
    float r; asm("ex2.approx.f32 %0, %1;" : "=f"(r) : "f"(x)); return r;
}
// 1/(1+u), u>=0 finite (magic seed + 2 Newton, rel err ~1.4e-6)
__device__ __forceinline__ float rcp1p(float u) {
    float den = 1.0f + u;
    float r = __uint_as_float(0x7ef311c3u - __float_as_uint(den));
    r = r * (2.0f - den * r);
    r = r * (2.0f - den * r);
    return r;
}
__device__ __forceinline__ float sigl(float zl) { return rcp1p(ex2f(-zl)); }
__device__ __forceinline__ float sigmoid_safe(float z) {
    z = fminf(fmaxf(z, -30.0f), 30.0f);
    return rcp1p(ex2f(-z * LOG2E));
}

// device-wide barrier (counters reset by trailing kernel)
__device__ __forceinline__ void gbar(int idx) {
    __syncthreads();
    if (threadIdx.x == 0) {
        __threadfence();
        atomicAdd(&g_bar[idx], 1u);
        while (*((volatile unsigned*)&g_bar[idx]) < GRID) __nanosleep(64);
    }
    __syncthreads();
}

__global__ void __launch_bounds__(TPB, 4) logicmp_fused(
    const float* __restrict__ S, const float* __restrict__ C,
    const float* __restrict__ F, const float* __restrict__ W,
    float* __restrict__ out)
{
    const int tid = threadIdx.x;
    const int bid = blockIdx.x;
    const int rowBase = bid * 8;
    const int bb = rowBase >> 11;              // batch of this block's rows
    const int cp = tid * 8;
    const int lane = tid & 31, warp = tid >> 5;
    const float w0 = W[0], w1 = W[1];

    __shared__ float sred[8][8];
    __shared__ float sh2[32][8];
    __shared__ float sm_s0[NN];

    // ================= phase PRE: d=(F1-F0)*log2e + fused iteration 0 =========
    {
        float s0c[8], m[8];
#pragma unroll
        for (int j = 0; j < 8; j++) {
            int c = bb * NN + cp + j;
            s0c[j] = 1.0f - sigmoid_safe(S[2 * c + 1] - S[2 * c]);
        }
#pragma unroll
        for (int r = 0; r < 8; r++) {
            int row = rowBase + r;
            m[r] = sigmoid_safe(S[2 * row + 1] - S[2 * row]);
        }
        float colsum[8] = {0,0,0,0,0,0,0,0};
        float racc[8];
        const float4* F4 = (const float4*)F;
#pragma unroll 2
        for (int r = 0; r < 8; r++) {
            const size_t row = rowBase + r;
            float4 f0 = __ldcs(&F4[row * 1024 + tid * 4 + 0]);
            float4 f1 = __ldcs(&F4[row * 1024 + tid * 4 + 1]);
            float4 f2 = __ldcs(&F4[row * 1024 + tid * 4 + 2]);
            float4 f3 = __ldcs(&F4[row * 1024 + tid * 4 + 3]);
            float zl[8];
            zl[0] = (f0.y - f0.x) * LOG2E; zl[1] = (f0.w - f0.z) * LOG2E;
            zl[2] = (f1.y - f1.x) * LOG2E; zl[3] = (f1.w - f1.z) * LOG2E;
            zl[4] = (f2.y - f2.x) * LOG2E; zl[5] = (f2.w - f2.z) * LOG2E;
            zl[6] = (f3.y - f3.x) * LOG2E; zl[7] = (f3.w - f3.z) * LOG2E;
            __half2 h0 = __floats2half2_rn(zl[0], zl[1]);
            __half2 h1 = __floats2half2_rn(zl[2], zl[3]);
            __half2 h2 = __floats2half2_rn(zl[4], zl[5]);
            __half2 h3 = __floats2half2_rn(zl[6], zl[7]);
            uint4 st;
            st.x = *(unsigned*)&h0; st.y = *(unsigned*)&h1;
            st.z = *(unsigned*)&h2; st.w = *(unsigned*)&h3;
            *(uint4*)&g_d[row * NN + cp] = st;
            float ra = 0.0f;
#pragma unroll
            for (int j = 0; j < 8; j++) {
                float q = sigl(zl[j]);
                ra = fmaf(q, s0c[j], ra);
                colsum[j] = fmaf(q, m[r], colsum[j]);
            }
            racc[r] = ra;
        }
#pragma unroll
        for (int r = 0; r < 8; r++) {
            float v = racc[r];
            v += __shfl_down_sync(~0u, v, 16);
            v += __shfl_down_sync(~0u, v, 8);
            v += __shfl_down_sync(~0u, v, 4);
            v += __shfl_down_sync(~0u, v, 2);
            v += __shfl_down_sync(~0u, v, 1);
            if (lane == 0) sred[r][warp] = v;
        }
        __syncthreads();
        if (tid < 8) {
            float v = 0.0f;
#pragma unroll
            for (int w = 0; w < 8; w++) v += sred[tid][w];
            g_A[rowBase + tid] = v;
        }
        *(float4*)&g_BvP[bid][cp]     = make_float4(colsum[0], colsum[1], colsum[2], colsum[3]);
        *(float4*)&g_BvP[bid][cp + 4] = make_float4(colsum[4], colsum[5], colsum[6], colsum[7]);
    }

    int bar = 0;
    // ================= iterations =================
    for (int k = 0; k <= 4; k++) {
        gbar(bar++);
        // ---- node phase: reduce BvP for my 8 nodes; update s1 (k<4) ----
        {
            const int node0 = bid * 8;
            const int nb = node0 >> 11;
            const int c0 = node0 & (NN - 1);
            const int ci = tid & 7, p0 = tid >> 3;       // p0 in 0..31
            const float* base = &g_BvP[nb * 256][c0 + ci];
            float s = 0.0f;
#pragma unroll
            for (int j = 0; j < 8; j++)
                s += __ldcg(base + (size_t)(p0 + j * 32) * NN);
            sh2[p0][ci] = s;
            __syncthreads();
            if (tid < 8) {
                float v = 0.0f;
#pragma unroll
                for (int p = 0; p < 32; p++) v += sh2[p][tid];
                const int i = node0 + tid;
                g_Bv[i] = v;
                if (k < 4) {
                    float Sd = S[2 * i + 1] - S[2 * i];
                    float Cd = C[2 * i] - C[2 * i + 1];
                    float c0k;
                    if (k == 0) {
                        c0k = sigmoid_safe(Cd);
                        g_s1[0][i] = sigmoid_safe(Sd);   // s1^0 table
                    } else {
                        float s1km1 = __ldcg(&g_s1[(k + 1) & 1][i]);
                        c0k = sigmoid_safe(Cd - w0 * s1km1);
                    }
                    float s1n = sigmoid_safe(Sd + w1 * v - w0 * c0k - w1 * __ldcg(&g_A[i]));
                    g_s1[(k + 1) & 1][i] = s1n;          // s1^{k+1}
                }
            }
            __syncthreads();
        }
        if (k == 4) break;
        gbar(bar++);

        // ---- iter phase k+1 ----
        {
            const int kk = k + 1;
            const int cur = kk & 1, prv = cur ^ 1;
            const float w1l = w1 * LOG2E;
            float s0c[8], s0p[8];
            {
                float4 c0v = __ldcg((const float4*)&g_s1[cur][bb * NN + cp]);
                float4 c1v = __ldcg((const float4*)&g_s1[cur][bb * NN + cp + 4]);
                float4 p0v = __ldcg((const float4*)&g_s1[prv][bb * NN + cp]);
                float4 p1v = __ldcg((const float4*)&g_s1[prv][bb * NN + cp + 4]);
                s0c[0]=1.f-c0v.x; s0c[1]=1.f-c0v.y; s0c[2]=1.f-c0v.z; s0c[3]=1.f-c0v.w;
                s0c[4]=1.f-c1v.x; s0c[5]=1.f-c1v.y; s0c[6]=1.f-c1v.z; s0c[7]=1.f-c1v.w;
                s0p[0]=1.f-p0v.x; s0p[1]=1.f-p0v.y; s0p[2]=1.f-p0v.z; s0p[3]=1.f-p0v.w;
                s0p[4]=1.f-p1v.x; s0p[5]=1.f-p1v.y; s0p[6]=1.f-p1v.z; s0p[7]=1.f-p1v.w;
            }
            float a2[8], m[8];
#pragma unroll
            for (int r = 0; r < 8; r++) {
                a2[r] = w1l * __ldcg(&g_s1[prv][rowBase + r]);
                m[r]  = __ldcg(&g_s1[cur][rowBase + r]);
            }
            uint4 dv[8];
            const __half* dp = g_d + (size_t)rowBase * NN + cp;
#pragma unroll
            for (int r = 0; r < 8; r++)
                dv[r] = *(const uint4*)(dp + (size_t)r * NN);

            float colsum[8] = {0,0,0,0,0,0,0,0};
            float racc[8];
#pragma unroll
            for (int r = 0; r < 8; r++) {
                float2 d01 = __half22float2(*(__half2*)&dv[r].x);
                float2 d23 = __half22float2(*(__half2*)&dv[r].y);
                float2 d45 = __half22float2(*(__half2*)&dv[r].z);
                float2 d67 = __half22float2(*(__half2*)&dv[r].w);
                float dd[8] = {d01.x, d01.y, d23.x, d23.y, d45.x, d45.y, d67.x, d67.y};
                float ra = 0.0f;
#pragma unroll
                for (int j = 0; j < 8; j++) {
                    float q = rcp1p(ex2f(fmaf(a2[r], s0p[j], -dd[j])));
                    ra = fmaf(q, s0c[j], ra);
                    colsum[j] = fmaf(q, m[r], colsum[j]);
                }
                racc[r] = ra;
            }
#pragma unroll
            for (int r = 0; r < 8; r++) {
                float v = racc[r];
                v += __shfl_down_sync(~0u, v, 16);
                v += __shfl_down_sync(~0u, v, 8);
                v += __shfl_down_sync(~0u, v, 4);
                v += __shfl_down_sync(~0u, v, 2);
                v += __shfl_down_sync(~0u, v, 1);
                if (lane == 0) sred[r][warp] = v;
            }
            __syncthreads();
            if (tid < 8) {
                float v = 0.0f;
#pragma unroll
                for (int w = 0; w < 8; w++) v += sred[tid][w];
                g_A[rowBase + tid] = v;
            }
            *(float4*)&g_BvP[bid][cp]     = make_float4(colsum[0], colsum[1], colsum[2], colsum[3]);
            *(float4*)&g_BvP[bid][cp + 4] = make_float4(colsum[4], colsum[5], colsum[6], colsum[7]);
            __syncthreads();
        }
    }

    gbar(bar++);   // after node phase k=4: s1^4, s1^3, A^4, Bv^4 all ready

    // ================= FINAL =================
    // out floats: [S: 8192][C: 8192][F: 16777216]; s1^4=g_s1[0], s1^3=g_s1[1]
    if (bid < 16) {
        const int i = bid * 256 + tid;
        float s13 = __ldcg(&g_s1[1][i]), s14 = __ldcg(&g_s1[0][i]);
        float Cd = C[2 * i] - C[2 * i + 1];
        float c04 = sigmoid_safe(Cd - w0 * s13);
        out[2 * i]     = S[2 * i] + w0 * c04 + w1 * __ldcg(&g_A[i]);
        out[2 * i + 1] = S[2 * i + 1] + w1 * __ldcg(&g_Bv[i]);
        out[8192 + 2 * i]     = C[2 * i];
        out[8192 + 2 * i + 1] = C[2 * i + 1] + w0 * s14;
    }
    // cache s0^4 for my batch's columns in smem
    for (int c = tid; c < NN; c += TPB)
        sm_s0[c] = 1.0f - __ldcg(&g_s1[0][bb * NN + c]);
    __syncthreads();
#pragma unroll 2
    for (int r = 0; r < 8; r++) {
        const int row = rowBase + r;
        const float a = w1 * __ldcg(&g_s1[0][row]);
        const float4* Fr = (const float4*)F + (size_t)row * 1024;
        float4* Or = (float4*)out + 4096 + (size_t)row * 1024;
#pragma unroll
        for (int u = 0; u < 4; u++) {
            const int i = tid + 256 * u;
            float4 f = __ldcs(&Fr[i]);
            f.x = fmaf(a, sm_s0[2 * i], f.x);
            f.z = fmaf(a, sm_s0[2 * i + 1], f.z);
            Or[i] = f;
        }
    }
}

// trailing reset: zero barrier counters for the next graph replay
__global__ void reset_kernel() {
    if (threadIdx.x < 16) g_bar[threadIdx.x] = 0;
}

extern "C" void kernel_launch(void* const* d_in, const int* in_sizes, int n_in,
                              void* d_out, int out_size)
{
    const float* S = (const float*)d_in[0];
    const float* C = (const float*)d_in[1];
    const float* F = (const float*)d_in[2];
    const float* W = (const float*)d_in[3];
    float* out = (float*)d_out;

    logicmp_fused<<<GRID, TPB>>>(S, C, F, W, out);
    reset_kernel<<<1, 32>>>();
}

// round 7
// speedup vs baseline: 1.1195x; 1.1195x over previous
#include <cuda_runtime.h>
#include <cuda_fp16.h>
#include <cstdint>

#define NN     2048
#define NODES  4096
#define NBLK   512                    // pre/iter blocks; 8 rows per block
#define LOG2E  1.4426950408889634f

// ---------------- device scratch ----------------
__device__ __align__(16) __half g_d[(size_t)NODES * NN];  // (F1-F0)*log2e fp16, 16.8MB
__device__ __align__(16) float  g_s1[2][NODES];           // s1 ping-pong
__device__ __align__(16) float  g_A[NODES];               // row sums
__device__ __align__(16) float  g_BvP[NBLK][NN];          // per-block column partials (4MB)

__device__ __forceinline__ float ex2f(float x) {
    float r; asm("ex2.approx.f32 %0, %1;" : "=f"(r) : "f"(x)); return r;
}
// 1/(1+u), u>=0: magic seed + 2 Newton steps (max rel err ~6e-6)
__device__ __forceinline__ float rcp1p(float u) {
    float den = 1.0f + u;
    float r = __uint_as_float(0x7ef311c3u - __float_as_uint(den));
    r = r * (2.0f - den * r);
    r = r * (2.0f - den * r);
    return r;
}
__device__ __forceinline__ float sigl(float zl) { return rcp1p(ex2f(-zl)); }
__device__ __forceinline__ float sigmoid_safe(float z) {
    z = fminf(fmaxf(z, -30.0f), 30.0f);
    return rcp1p(ex2f(-z * LOG2E));
}

// ---------------- pre: d=(F1-F0)*log2e (fp16) + fused iteration 0 ------------
__global__ void __launch_bounds__(256) pre_kernel(
    const float* __restrict__ S, const float* __restrict__ F)
{
    const int tid = threadIdx.x;
    const int rowBase = blockIdx.x * 8;
    const int b = rowBase >> 11;
    const int cp = tid * 8;
    const int lane = tid & 31, warp = tid >> 5;

    float s0c[8], m[8];
#pragma unroll
    for (int j = 0; j < 8; j++) {
        int c = b * NN + cp + j;
        s0c[j] = 1.0f - sigmoid_safe(S[2 * c + 1] - S[2 * c]);
    }
#pragma unroll
    for (int r = 0; r < 8; r++) {
        int row = rowBase + r;
        m[r] = sigmoid_safe(S[2 * row + 1] - S[2 * row]);
    }

    float colsum[8] = {0,0,0,0,0,0,0,0};
    float racc[8];
    const float4* F4 = (const float4*)F;

#pragma unroll 2
    for (int r = 0; r < 8; r++) {
        const size_t row = rowBase + r;
        float4 f0 = __ldcs(&F4[row * 1024 + tid * 4 + 0]);
        float4 f1 = __ldcs(&F4[row * 1024 + tid * 4 + 1]);
        float4 f2 = __ldcs(&F4[row * 1024 + tid * 4 + 2]);
        float4 f3 = __ldcs(&F4[row * 1024 + tid * 4 + 3]);
        float zl[8];
        zl[0] = (f0.y - f0.x) * LOG2E; zl[1] = (f0.w - f0.z) * LOG2E;
        zl[2] = (f1.y - f1.x) * LOG2E; zl[3] = (f1.w - f1.z) * LOG2E;
        zl[4] = (f2.y - f2.x) * LOG2E; zl[5] = (f2.w - f2.z) * LOG2E;
        zl[6] = (f3.y - f3.x) * LOG2E; zl[7] = (f3.w - f3.z) * LOG2E;

        __half2 h0 = __floats2half2_rn(zl[0], zl[1]);
        __half2 h1 = __floats2half2_rn(zl[2], zl[3]);
        __half2 h2 = __floats2half2_rn(zl[4], zl[5]);
        __half2 h3 = __floats2half2_rn(zl[6], zl[7]);
        uint4 st;
        st.x = *(unsigned*)&h0; st.y = *(unsigned*)&h1;
        st.z = *(unsigned*)&h2; st.w = *(unsigned*)&h3;
        *(uint4*)&g_d[row * NN + cp] = st;

        float ra = 0.0f;
#pragma unroll
        for (int j = 0; j < 8; j++) {
            float q = sigl(zl[j]);
            ra = fmaf(q, s0c[j], ra);
            colsum[j] = fmaf(q, m[r], colsum[j]);
        }
        racc[r] = ra;
    }

    __shared__ float sred[8][8];
#pragma unroll
    for (int r = 0; r < 8; r++) {
        float v = racc[r];
        v += __shfl_down_sync(~0u, v, 16);
        v += __shfl_down_sync(~0u, v, 8);
        v += __shfl_down_sync(~0u, v, 4);
        v += __shfl_down_sync(~0u, v, 2);
        v += __shfl_down_sync(~0u, v, 1);
        if (lane == 0) sred[r][warp] = v;
    }
    __syncthreads();
    if (tid < 8) {
        float v = 0.0f;
#pragma unroll
        for (int w = 0; w < 8; w++) v += sred[tid][w];
        g_A[rowBase + tid] = v;
    }
    *(float4*)&g_BvP[blockIdx.x][cp]     = make_float4(colsum[0], colsum[1], colsum[2], colsum[3]);
    *(float4*)&g_BvP[blockIdx.x][cp + 4] = make_float4(colsum[4], colsum[5], colsum[6], colsum[7]);
}

// ---------------- iter k=1..4 -------------------------------------------------
__global__ void __launch_bounds__(256) iter_kernel(
    const float* __restrict__ W, int k)
{
    const int tid = threadIdx.x;
    const int rowBase = blockIdx.x * 8;
    const int b = rowBase >> 11;
    const int cp = tid * 8;
    const int cur = k & 1, prv = cur ^ 1;
    const int lane = tid & 31, warp = tid >> 5;
    const float w1l = W[1] * LOG2E;

    float s0c[8], s0p[8];
    {
        float4 c0 = *(const float4*)&g_s1[cur][b * NN + cp];
        float4 c1 = *(const float4*)&g_s1[cur][b * NN + cp + 4];
        float4 p0 = *(const float4*)&g_s1[prv][b * NN + cp];
        float4 p1 = *(const float4*)&g_s1[prv][b * NN + cp + 4];
        s0c[0]=1.f-c0.x; s0c[1]=1.f-c0.y; s0c[2]=1.f-c0.z; s0c[3]=1.f-c0.w;
        s0c[4]=1.f-c1.x; s0c[5]=1.f-c1.y; s0c[6]=1.f-c1.z; s0c[7]=1.f-c1.w;
        s0p[0]=1.f-p0.x; s0p[1]=1.f-p0.y; s0p[2]=1.f-p0.z; s0p[3]=1.f-p0.w;
        s0p[4]=1.f-p1.x; s0p[5]=1.f-p1.y; s0p[6]=1.f-p1.z; s0p[7]=1.f-p1.w;
    }
    float a2[8], m[8];
#pragma unroll
    for (int r = 0; r < 8; r++) {
        a2[r] = w1l * g_s1[prv][rowBase + r];
        m[r]  = g_s1[cur][rowBase + r];
    }

    uint4 dv[8];
    const __half* dp = g_d + (size_t)rowBase * NN + cp;
#pragma unroll
    for (int r = 0; r < 8; r++)
        dv[r] = *(const uint4*)(dp + (size_t)r * NN);

    float colsum[8] = {0,0,0,0,0,0,0,0};
    float racc[8];
#pragma unroll
    for (int r = 0; r < 8; r++) {
        float2 d01 = __half22float2(*(__half2*)&dv[r].x);
        float2 d23 = __half22float2(*(__half2*)&dv[r].y);
        float2 d45 = __half22float2(*(__half2*)&dv[r].z);
        float2 d67 = __half22float2(*(__half2*)&dv[r].w);
        float dd[8] = {d01.x, d01.y, d23.x, d23.y, d45.x, d45.y, d67.x, d67.y};
        float ra = 0.0f;
#pragma unroll
        for (int j = 0; j < 8; j++) {
            float q = rcp1p(ex2f(fmaf(a2[r], s0p[j], -dd[j])));
            ra = fmaf(q, s0c[j], ra);
            colsum[j] = fmaf(q, m[r], colsum[j]);
        }
        racc[r] = ra;
    }

    __shared__ float sred[8][8];
#pragma unroll
    for (int r = 0; r < 8; r++) {
        float v = racc[r];
        v += __shfl_down_sync(~0u, v, 16);
        v += __shfl_down_sync(~0u, v, 8);
        v += __shfl_down_sync(~0u, v, 4);
        v += __shfl_down_sync(~0u, v, 2);
        v += __shfl_down_sync(~0u, v, 1);
        if (lane == 0) sred[r][warp] = v;
    }
    __syncthreads();
    if (tid < 8) {
        float v = 0.0f;
#pragma unroll
        for (int w = 0; w < 8; w++) v += sred[tid][w];
        g_A[rowBase + tid] = v;
    }
    *(float4*)&g_BvP[blockIdx.x][cp]     = make_float4(colsum[0], colsum[1], colsum[2], colsum[3]);
    *(float4*)&g_BvP[blockIdx.x][cp + 4] = make_float4(colsum[4], colsum[5], colsum[6], colsum[7]);
}

// ---------------- node k=0..3: reduce BvP + s1^{k+1} --------------------------
// grid 512 x 256: block = 8 nodes; thread (ci=tid&7, pg=tid>>3) sums 8 partials.
__global__ void __launch_bounds__(256) node_kernel(
    const float* __restrict__ S, const float* __restrict__ C,
    const float* __restrict__ W, int k)
{
    const int tid = threadIdx.x;
    const int node0 = blockIdx.x * 8;
    const int b = node0 >> 11;
    const int c0 = node0 & (NN - 1);
    const int ci = tid & 7, pg = tid >> 3;        // pg in 0..31
    const float* base = &g_BvP[b * 256 + pg][c0 + ci];
    float s = 0.0f;
#pragma unroll
    for (int j = 0; j < 8; j++)                   // front-batched, stride 32 rows
        s += base[(size_t)(32 * j) * NN];
    __shared__ float sh[32][8];
    sh[pg][ci] = s;
    __syncthreads();
    if (tid < 8) {
        float v = 0.0f;
#pragma unroll
        for (int p = 0; p < 32; p++) v += sh[p][tid];
        const int i = node0 + tid;
        const float w0 = W[0], w1 = W[1];
        const float Sd = S[2 * i + 1] - S[2 * i];
        const float Cd = C[2 * i] - C[2 * i + 1];
        float c0k;
        if (k == 0) {
            c0k = sigmoid_safe(Cd);
            g_s1[0][i] = sigmoid_safe(Sd);        // s1^0 table
        } else {
            float s1km1 = g_s1[(k + 1) & 1][i];   // s1^{k-1} (read before overwrite)
            c0k = sigmoid_safe(Cd - w0 * s1km1);
        }
        float s1n = sigmoid_safe(Sd + w1 * v - w0 * c0k - w1 * g_A[i]);
        g_s1[(k + 1) & 1][i] = s1n;               // s1^{k+1}
    }
}

// ---------------- final: F outputs + fused Bv^4 reduction + S/C outputs -------
// out floats: [S: 8192][C: 8192][F: 16777216]; s1^4=g_s1[0], s1^3=g_s1[1]
__global__ void __launch_bounds__(256) final_kernel(
    const float* __restrict__ S, const float* __restrict__ C,
    const float* __restrict__ F, const float* __restrict__ W,
    float* __restrict__ out)
{
    const int row = blockIdx.x;
    const int b = row >> 11;
    const int tid = threadIdx.x;
    const float w0 = W[0], w1 = W[1];
    const float a = w1 * g_s1[0][row];
    const float4* Fr = (const float4*)F + (size_t)row * 1024;
    float4* Or = (float4*)out + 4096 + (size_t)row * 1024;
    const float* s1col = &g_s1[0][b * NN];

    float4 f[4]; float2 s[4];
#pragma unroll
    for (int u = 0; u < 4; u++) {
        int i = tid + 256 * u;
        f[u] = __ldcs(&Fr[i]);
        s[u] = *(const float2*)&s1col[2 * i];
    }
#pragma unroll
    for (int u = 0; u < 4; u++) {
        int i = tid + 256 * u;
        f[u].x = fmaf(a, 1.0f - s[u].x, f[u].x);
        f[u].z = fmaf(a, 1.0f - s[u].y, f[u].z);
        Or[i] = f[u];
    }
    if (row < 16) {
        const int i = row * 256 + tid;
        const int bb = i >> 11, c = i & (NN - 1);
        // reduce Bv^4[i] over 256 partials, coalesced, 8 accumulators
        const float* base = &g_BvP[bb * 256][c];
        float acc[8] = {0,0,0,0,0,0,0,0};
#pragma unroll 4
        for (int p0 = 0; p0 < 256; p0 += 8) {
#pragma unroll
            for (int j = 0; j < 8; j++)
                acc[j] += base[(size_t)(p0 + j) * NN];
        }
        float v = ((acc[0] + acc[1]) + (acc[2] + acc[3])) +
                  ((acc[4] + acc[5]) + (acc[6] + acc[7]));
        float s13 = g_s1[1][i], s14 = g_s1[0][i];
        float Cd = C[2 * i] - C[2 * i + 1];
        float c04 = sigmoid_safe(Cd - w0 * s13);
        out[2 * i]     = S[2 * i] + w0 * c04 + w1 * g_A[i];
        out[2 * i + 1] = S[2 * i + 1] + w1 * v;
        out[8192 + 2 * i]     = C[2 * i];
        out[8192 + 2 * i + 1] = C[2 * i + 1] + w0 * s14;
    }
}

extern "C" void kernel_launch(void* const* d_in, const int* in_sizes, int n_in,
                              void* d_out, int out_size)
{
    const float* S = (const float*)d_in[0];
    const float* C = (const float*)d_in[1];
    const float* F = (const float*)d_in[2];
    const float* W = (const float*)d_in[3];
    float* out = (float*)d_out;

    pre_kernel<<<NBLK, 256>>>(S, F);             // d + iteration-0 sums
    node_kernel<<<NBLK, 256>>>(S, C, W, 0);      // s1^1
    for (int k = 1; k <= 4; k++) {
        iter_kernel<<<NBLK, 256>>>(W, k);
        if (k < 4) node_kernel<<<NBLK, 256>>>(S, C, W, k);  // s1^{k+1}
    }
    final_kernel<<<4096, 256>>>(S, C, F, W, out);  // fuses Bv^4 reduce
}

// round 8
// speedup vs baseline: 1.2524x; 1.1187x over previous
#include <cuda_runtime.h>
#include <cuda_fp16.h>
#include <cstdint>

#define NN     2048
#define NODES  4096
#define RGS    64                     // row-groups (64 rows each)
#define CGS    8                      // col-groups (256 cols each)
#define NBLK   (RGS * CGS)            // 512 blocks for pre/iter
#define LOG2E  1.4426950408889634f

// ---------------- device scratch ----------------
__device__ __align__(16) __half g_d[(size_t)NODES * NN];  // (F1-F0)*log2e fp16, 16.8MB
__device__ __align__(16) float  g_s1[2][NODES];           // s1 ping-pong
__device__ __align__(16) float  g_AP[CGS][NODES];         // A partials (128KB)
__device__ __align__(16) float  g_BvP[RGS][NN];           // Bv partials (512KB)

__device__ __forceinline__ float ex2f(float x) {
    float r; asm("ex2.approx.f32 %0, %1;" : "=f"(r) : "f"(x)); return r;
}
// 1/(1+u), u>=0: magic seed + 2 Newton steps (max rel err ~6e-6)
__device__ __forceinline__ float rcp1p(float u) {
    float den = 1.0f + u;
    float r = __uint_as_float(0x7ef311c3u - __float_as_uint(den));
    r = r * (2.0f - den * r);
    r = r * (2.0f - den * r);
    return r;
}
__device__ __forceinline__ float sigl(float zl) { return rcp1p(ex2f(-zl)); }
__device__ __forceinline__ float sigmoid_safe(float z) {
    z = fminf(fmaxf(z, -30.0f), 30.0f);
    return rcp1p(ex2f(-z * LOG2E));
}

// ---------------- pre: d=(F1-F0)*log2e (fp16) + fused iteration 0 ------------
// block (rg, cg): rows [rg*64, rg*64+64), cols [cg*256, cg*256+256) of batch.
// thread (ci=tid&31, rs=tid>>5): 8 rows (rs*8..) x 8 cols (ci*8..).
__global__ void __launch_bounds__(256) pre_kernel(
    const float* __restrict__ S, const float* __restrict__ F)
{
    const int tid = threadIdx.x;
    const int rg = blockIdx.x >> 3, cg = blockIdx.x & 7;
    const int rowBase = rg * 64;
    const int b = rowBase >> 11;
    const int ci = tid & 31, rs = tid >> 5;
    const int c8 = cg * 256 + ci * 8;            // col within batch
    const int gc = b * NN + c8;                  // global node idx of first col
    const int rBase = rowBase + rs * 8;

    float s0c[8], m[8];
#pragma unroll
    for (int j = 0; j < 8; j++)
        s0c[j] = 1.0f - sigmoid_safe(S[2 * (gc + j) + 1] - S[2 * (gc + j)]);
#pragma unroll
    for (int r = 0; r < 8; r++) {
        int row = rBase + r;
        m[r] = sigmoid_safe(S[2 * row + 1] - S[2 * row]);
    }

    float colsum[8] = {0,0,0,0,0,0,0,0};
    const float4* F4 = (const float4*)F;

#pragma unroll 2
    for (int r = 0; r < 8; r++) {
        const size_t row = rBase + r;
        const size_t fo = row * 1024 + (c8 >> 1);
        float4 f0 = __ldcs(&F4[fo + 0]);
        float4 f1 = __ldcs(&F4[fo + 1]);
        float4 f2 = __ldcs(&F4[fo + 2]);
        float4 f3 = __ldcs(&F4[fo + 3]);
        float zl[8];
        zl[0] = (f0.y - f0.x) * LOG2E; zl[1] = (f0.w - f0.z) * LOG2E;
        zl[2] = (f1.y - f1.x) * LOG2E; zl[3] = (f1.w - f1.z) * LOG2E;
        zl[4] = (f2.y - f2.x) * LOG2E; zl[5] = (f2.w - f2.z) * LOG2E;
        zl[6] = (f3.y - f3.x) * LOG2E; zl[7] = (f3.w - f3.z) * LOG2E;

        __half2 h0 = __floats2half2_rn(zl[0], zl[1]);
        __half2 h1 = __floats2half2_rn(zl[2], zl[3]);
        __half2 h2 = __floats2half2_rn(zl[4], zl[5]);
        __half2 h3 = __floats2half2_rn(zl[6], zl[7]);
        uint4 st;
        st.x = *(unsigned*)&h0; st.y = *(unsigned*)&h1;
        st.z = *(unsigned*)&h2; st.w = *(unsigned*)&h3;
        *(uint4*)&g_d[row * NN + c8] = st;

        float ra = 0.0f;
#pragma unroll
        for (int j = 0; j < 8; j++) {
            float q = sigl(zl[j]);
            ra = fmaf(q, s0c[j], ra);
            colsum[j] = fmaf(q, m[r], colsum[j]);
        }
        // all 32 lanes of this warp share row -> pure shuffle reduce
        ra += __shfl_down_sync(~0u, ra, 16);
        ra += __shfl_down_sync(~0u, ra, 8);
        ra += __shfl_down_sync(~0u, ra, 4);
        ra += __shfl_down_sync(~0u, ra, 2);
        ra += __shfl_down_sync(~0u, ra, 1);
        if (ci == 0) g_AP[cg][row] = ra;
    }

    __shared__ float sh[8][256];
#pragma unroll
    for (int j = 0; j < 8; j++) sh[rs][ci * 8 + j] = colsum[j];
    __syncthreads();
    float v = 0.0f;
#pragma unroll
    for (int s = 0; s < 8; s++) v += sh[s][tid];
    g_BvP[rg][cg * 256 + tid] = v;
}

// ---------------- iter k=1..4 -------------------------------------------------
__global__ void __launch_bounds__(256) iter_kernel(
    const float* __restrict__ W, int k)
{
    const int tid = threadIdx.x;
    const int rg = blockIdx.x >> 3, cg = blockIdx.x & 7;
    const int rowBase = rg * 64;
    const int b = rowBase >> 11;
    const int ci = tid & 31, rs = tid >> 5;
    const int c8 = cg * 256 + ci * 8;
    const int gc = b * NN + c8;
    const int rBase = rowBase + rs * 8;
    const int cur = k & 1, prv = cur ^ 1;
    const float w1l = W[1] * LOG2E;

    float s0c[8], s0p[8];
    {
        float4 c0 = *(const float4*)&g_s1[cur][gc];
        float4 c1 = *(const float4*)&g_s1[cur][gc + 4];
        float4 p0 = *(const float4*)&g_s1[prv][gc];
        float4 p1 = *(const float4*)&g_s1[prv][gc + 4];
        s0c[0]=1.f-c0.x; s0c[1]=1.f-c0.y; s0c[2]=1.f-c0.z; s0c[3]=1.f-c0.w;
        s0c[4]=1.f-c1.x; s0c[5]=1.f-c1.y; s0c[6]=1.f-c1.z; s0c[7]=1.f-c1.w;
        s0p[0]=1.f-p0.x; s0p[1]=1.f-p0.y; s0p[2]=1.f-p0.z; s0p[3]=1.f-p0.w;
        s0p[4]=1.f-p1.x; s0p[5]=1.f-p1.y; s0p[6]=1.f-p1.z; s0p[7]=1.f-p1.w;
    }
    float a2[8], m[8];
#pragma unroll
    for (int r = 0; r < 8; r++) {
        a2[r] = w1l * g_s1[prv][rBase + r];
        m[r]  = g_s1[cur][rBase + r];
    }

    uint4 dv[8];
    const __half* dp = g_d + (size_t)rBase * NN + c8;
#pragma unroll
    for (int r = 0; r < 8; r++)
        dv[r] = *(const uint4*)(dp + (size_t)r * NN);

    float colsum[8] = {0,0,0,0,0,0,0,0};
#pragma unroll
    for (int r = 0; r < 8; r++) {
        float2 d01 = __half22float2(*(__half2*)&dv[r].x);
        float2 d23 = __half22float2(*(__half2*)&dv[r].y);
        float2 d45 = __half22float2(*(__half2*)&dv[r].z);
        float2 d67 = __half22float2(*(__half2*)&dv[r].w);
        float dd[8] = {d01.x, d01.y, d23.x, d23.y, d45.x, d45.y, d67.x, d67.y};
        float ra = 0.0f;
#pragma unroll
        for (int j = 0; j < 8; j++) {
            float q = rcp1p(ex2f(fmaf(a2[r], s0p[j], -dd[j])));
            ra = fmaf(q, s0c[j], ra);
            colsum[j] = fmaf(q, m[r], colsum[j]);
        }
        ra += __shfl_down_sync(~0u, ra, 16);
        ra += __shfl_down_sync(~0u, ra, 8);
        ra += __shfl_down_sync(~0u, ra, 4);
        ra += __shfl_down_sync(~0u, ra, 2);
        ra += __shfl_down_sync(~0u, ra, 1);
        if (ci == 0) g_AP[cg][rBase + r] = ra;
    }

    __shared__ float sh[8][256];
#pragma unroll
    for (int j = 0; j < 8; j++) sh[rs][ci * 8 + j] = colsum[j];
    __syncthreads();
    float v = 0.0f;
#pragma unroll
    for (int s = 0; s < 8; s++) v += sh[s][tid];
    g_BvP[rg][cg * 256 + tid] = v;
}

// ---------------- node k=0..3: reduce AP,BvP + s1^{k+1} -----------------------
// grid 16 x 256: thread = one node. 32 Bv partials + 8 A partials, coalesced.
__global__ void __launch_bounds__(256) node_kernel(
    const float* __restrict__ S, const float* __restrict__ C,
    const float* __restrict__ W, int k)
{
    const int i = blockIdx.x * 256 + threadIdx.x;
    const int b = i >> 11, c = i & (NN - 1);
    const float* bp = &g_BvP[b * 32][c];
    float bv = 0.0f;
#pragma unroll
    for (int j = 0; j < 32; j++) bv += bp[(size_t)j * NN];
    float Av = 0.0f;
#pragma unroll
    for (int g = 0; g < CGS; g++) Av += g_AP[g][i];

    const float w0 = W[0], w1 = W[1];
    const float Sd = S[2 * i + 1] - S[2 * i];
    const float Cd = C[2 * i] - C[2 * i + 1];
    float c0k;
    if (k == 0) {
        c0k = sigmoid_safe(Cd);
        g_s1[0][i] = sigmoid_safe(Sd);            // s1^0 table
    } else {
        float s1km1 = g_s1[(k + 1) & 1][i];       // s1^{k-1}
        c0k = sigmoid_safe(Cd - w0 * s1km1);
    }
    float s1n = sigmoid_safe(Sd + w1 * bv - w0 * c0k - w1 * Av);
    g_s1[(k + 1) & 1][i] = s1n;                   // s1^{k+1}
}

// ---------------- final: F outputs + fused A^4/Bv^4 reduction + S/C -----------
// out floats: [S: 8192][C: 8192][F: 16777216]; s1^4=g_s1[0], s1^3=g_s1[1]
__global__ void __launch_bounds__(256) final_kernel(
    const float* __restrict__ S, const float* __restrict__ C,
    const float* __restrict__ F, const float* __restrict__ W,
    float* __restrict__ out)
{
    const int row = blockIdx.x;
    const int b = row >> 11;
    const int tid = threadIdx.x;
    const float w0 = W[0], w1 = W[1];
    const float a = w1 * g_s1[0][row];
    const float4* Fr = (const float4*)F + (size_t)row * 1024;
    float4* Or = (float4*)out + 4096 + (size_t)row * 1024;
    const float* s1col = &g_s1[0][b * NN];

    float4 f[4]; float2 s[4];
#pragma unroll
    for (int u = 0; u < 4; u++) {
        int i = tid + 256 * u;
        f[u] = __ldcs(&Fr[i]);
        s[u] = *(const float2*)&s1col[2 * i];
    }
#pragma unroll
    for (int u = 0; u < 4; u++) {
        int i = tid + 256 * u;
        f[u].x = fmaf(a, 1.0f - s[u].x, f[u].x);
        f[u].z = fmaf(a, 1.0f - s[u].y, f[u].z);
        Or[i] = f[u];
    }
    if (row < 16) {
        const int i = row * 256 + tid;
        const int bb = i >> 11, c = i & (NN - 1);
        const float* bp = &g_BvP[bb * 32][c];
        float bv = 0.0f;
#pragma unroll
        for (int j = 0; j < 32; j++) bv += bp[(size_t)j * NN];
        float Av = 0.0f;
#pragma unroll
        for (int g = 0; g < CGS; g++) Av += g_AP[g][i];

        float s13 = g_s1[1][i], s14 = g_s1[0][i];
        float Cd = C[2 * i] - C[2 * i + 1];
        float c04 = sigmoid_safe(Cd - w0 * s13);
        out[2 * i]     = S[2 * i] + w0 * c04 + w1 * Av;
        out[2 * i + 1] = S[2 * i + 1] + w1 * bv;
        out[8192 + 2 * i]     = C[2 * i];
        out[8192 + 2 * i + 1] = C[2 * i + 1] + w0 * s14;
    }
}

extern "C" void kernel_launch(void* const* d_in, const int* in_sizes, int n_in,
                              void* d_out, int out_size)
{
    const float* S = (const float*)d_in[0];
    const float* C = (const float*)d_in[1];
    const float* F = (const float*)d_in[2];
    const float* W = (const float*)d_in[3];
    float* out = (float*)d_out;

    pre_kernel<<<NBLK, 256>>>(S, F);             // d + iteration-0 partials
    node_kernel<<<16, 256>>>(S, C, W, 0);        // s1^1
    for (int k = 1; k <= 4; k++) {
        iter_kernel<<<NBLK, 256>>>(W, k);
        if (k < 4) node_kernel<<<16, 256>>>(S, C, W, k);
    }
    final_kernel<<<4096, 256>>>(S, C, F, W, out);  // fuses A^4/Bv^4 reduce
}

// round 9
// speedup vs baseline: 1.2705x; 1.0145x over previous
#include <cuda_runtime.h>
#include <cuda_fp16.h>
#include <cstdint>

#define NN     2048
#define NODES  4096
#define RGS    64                     // row-groups (64 rows each)
#define CGS    8                      // col-groups (256 cols each)
#define NBLK   (RGS * CGS)            // 512 blocks for pre/iter
#define LOG2E  1.4426950408889634f

// ---------------- device scratch ----------------
__device__ __align__(16) __half g_d[(size_t)NODES * NN];  // (F1-F0)*log2e fp16, 16.8MB
__device__ __align__(16) float  g_tab[5][NODES];          // s1^0..s1^4 tables (80KB)
__device__ __align__(16) float  g_AP[2][CGS][NODES];      // A partials, parity-buffered
__device__ __align__(16) float  g_BvP[2][RGS][NN];        // Bv partials, parity-buffered

__device__ __forceinline__ float ex2f(float x) {
    float r; asm("ex2.approx.f32 %0, %1;" : "=f"(r) : "f"(x)); return r;
}
// 1/(1+u), u>=0: magic seed + 2 Newton steps (max rel err ~6e-6)
__device__ __forceinline__ float rcp1p(float u) {
    float den = 1.0f + u;
    float r = __uint_as_float(0x7ef311c3u - __float_as_uint(den));
    r = r * (2.0f - den * r);
    r = r * (2.0f - den * r);
    return r;
}
__device__ __forceinline__ float sigl(float zl) { return rcp1p(ex2f(-zl)); }
__device__ __forceinline__ float sigmoid_safe(float z) {
    z = fminf(fmaxf(z, -30.0f), 30.0f);
    return rcp1p(ex2f(-z * LOG2E));
}

// ---------------- pre: d=(F1-F0)*log2e (fp16) + fused iteration 0 ------------
// block (rg, cg): rows [rg*64, +64), cols [cg*256, +256); thread: 8 rows x 8 cols
__global__ void __launch_bounds__(256) pre_kernel(
    const float* __restrict__ S, const float* __restrict__ F)
{
    const int tid = threadIdx.x;
    const int rg = blockIdx.x >> 3, cg = blockIdx.x & 7;
    const int rowBase = rg * 64;
    const int b = rowBase >> 11;
    const int ci = tid & 31, rs = tid >> 5;
    const int c8 = cg * 256 + ci * 8;
    const int gc = b * NN + c8;
    const int rBase = rowBase + rs * 8;

    float s0c[8], m[8];
#pragma unroll
    for (int j = 0; j < 8; j++)
        s0c[j] = 1.0f - sigmoid_safe(S[2 * (gc + j) + 1] - S[2 * (gc + j)]);
#pragma unroll
    for (int r = 0; r < 8; r++) {
        int row = rBase + r;
        m[r] = sigmoid_safe(S[2 * row + 1] - S[2 * row]);
    }
    // writer blocks materialize s1^0 table
    if (cg == 0 && tid < 64) {
        int i2 = rowBase + tid;
        g_tab[0][i2] = sigmoid_safe(S[2 * i2 + 1] - S[2 * i2]);
    }

    float colsum[8] = {0,0,0,0,0,0,0,0};
    const float4* F4 = (const float4*)F;

#pragma unroll 2
    for (int r = 0; r < 8; r++) {
        const size_t row = rBase + r;
        const size_t fo = row * 1024 + (c8 >> 1);
        float4 f0 = __ldcs(&F4[fo + 0]);
        float4 f1 = __ldcs(&F4[fo + 1]);
        float4 f2 = __ldcs(&F4[fo + 2]);
        float4 f3 = __ldcs(&F4[fo + 3]);
        float zl[8];
        zl[0] = (f0.y - f0.x) * LOG2E; zl[1] = (f0.w - f0.z) * LOG2E;
        zl[2] = (f1.y - f1.x) * LOG2E; zl[3] = (f1.w - f1.z) * LOG2E;
        zl[4] = (f2.y - f2.x) * LOG2E; zl[5] = (f2.w - f2.z) * LOG2E;
        zl[6] = (f3.y - f3.x) * LOG2E; zl[7] = (f3.w - f3.z) * LOG2E;

        __half2 h0 = __floats2half2_rn(zl[0], zl[1]);
        __half2 h1 = __floats2half2_rn(zl[2], zl[3]);
        __half2 h2 = __floats2half2_rn(zl[4], zl[5]);
        __half2 h3 = __floats2half2_rn(zl[6], zl[7]);
        uint4 st;
        st.x = *(unsigned*)&h0; st.y = *(unsigned*)&h1;
        st.z = *(unsigned*)&h2; st.w = *(unsigned*)&h3;
        *(uint4*)&g_d[row * NN + c8] = st;

        float ra = 0.0f;
#pragma unroll
        for (int j = 0; j < 8; j++) {
            float q = sigl(zl[j]);
            ra = fmaf(q, s0c[j], ra);
            colsum[j] = fmaf(q, m[r], colsum[j]);
        }
        ra += __shfl_down_sync(~0u, ra, 16);
        ra += __shfl_down_sync(~0u, ra, 8);
        ra += __shfl_down_sync(~0u, ra, 4);
        ra += __shfl_down_sync(~0u, ra, 2);
        ra += __shfl_down_sync(~0u, ra, 1);
        if (ci == 0) g_AP[0][cg][row] = ra;
    }

    __shared__ float sh[8][256];
#pragma unroll
    for (int j = 0; j < 8; j++) sh[rs][ci * 8 + j] = colsum[j];
    __syncthreads();
    float v = 0.0f;
#pragma unroll
    for (int s = 0; s < 8; s++) v += sh[s][tid];
    g_BvP[0][rg][cg * 256 + tid] = v;
}

// ---------------- iter j=1..4: fused node recompute + matvec ------------------
__global__ void __launch_bounds__(256) iter_kernel(
    const float* __restrict__ S, const float* __restrict__ C,
    const float* __restrict__ W, int j)
{
    const int tid = threadIdx.x;
    const int rg = blockIdx.x >> 3, cg = blockIdx.x & 7;
    const int rowBase = rg * 64;
    const int b = rowBase >> 11;
    const int ci = tid & 31, rs = tid >> 5;
    const int c8 = cg * 256 + ci * 8;
    const int gc = b * NN + c8;
    const int rBase = rowBase + rs * 8;
    const int rp = (j - 1) & 1, wp = j & 1;
    const int jm2 = (j >= 2) ? j - 2 : 0;
    const float w0 = W[0], w1 = W[1];
    const float w1l = w1 * LOG2E;

    // ---- redundant node update: s1^j for my 256 cols + 64 rows ----
    __shared__ float smc[256], smr[64];
    {
        const int i = b * NN + cg * 256 + tid;     // col node
        float bv = 0.0f;
#pragma unroll
        for (int t = 0; t < 32; t++) bv += g_BvP[rp][b * 32 + t][cg * 256 + tid];
        float Av = 0.0f;
#pragma unroll
        for (int g = 0; g < CGS; g++) Av += g_AP[rp][g][i];
        float Sd = S[2 * i + 1] - S[2 * i];
        float Cd = C[2 * i] - C[2 * i + 1];
        float c0 = (j == 1) ? sigmoid_safe(Cd)
                            : sigmoid_safe(Cd - w0 * g_tab[jm2][i]);
        smc[tid] = sigmoid_safe(Sd + w1 * bv - w0 * c0 - w1 * Av);
    }
    if (tid < 64) {
        const int i2 = rowBase + tid;              // row node (same batch b)
        const int c2 = i2 & (NN - 1);
        float bv = 0.0f;
#pragma unroll
        for (int t = 0; t < 32; t++) bv += g_BvP[rp][b * 32 + t][c2];
        float Av = 0.0f;
#pragma unroll
        for (int g = 0; g < CGS; g++) Av += g_AP[rp][g][i2];
        float Sd = S[2 * i2 + 1] - S[2 * i2];
        float Cd = C[2 * i2] - C[2 * i2 + 1];
        float c0 = (j == 1) ? sigmoid_safe(Cd)
                            : sigmoid_safe(Cd - w0 * g_tab[jm2][i2]);
        float vv = sigmoid_safe(Sd + w1 * bv - w0 * c0 - w1 * Av);
        smr[tid] = vv;
        if (cg == 0) g_tab[j][i2] = vv;            // materialize for next launch
    }
    __syncthreads();

    // ---- mainloop ----
    float s0c[8], s0p[8];
#pragma unroll
    for (int q = 0; q < 8; q++) s0c[q] = 1.0f - smc[ci * 8 + q];
    {
        float4 p0 = *(const float4*)&g_tab[j - 1][gc];
        float4 p1 = *(const float4*)&g_tab[j - 1][gc + 4];
        s0p[0]=1.f-p0.x; s0p[1]=1.f-p0.y; s0p[2]=1.f-p0.z; s0p[3]=1.f-p0.w;
        s0p[4]=1.f-p1.x; s0p[5]=1.f-p1.y; s0p[6]=1.f-p1.z; s0p[7]=1.f-p1.w;
    }
    float a2[8], m[8];
#pragma unroll
    for (int r = 0; r < 8; r++) {
        a2[r] = w1l * g_tab[j - 1][rBase + r];
        m[r]  = smr[rs * 8 + r];
    }

    uint4 dv[8];
    const __half* dp = g_d + (size_t)rBase * NN + c8;
#pragma unroll
    for (int r = 0; r < 8; r++)
        dv[r] = *(const uint4*)(dp + (size_t)r * NN);

    float colsum[8] = {0,0,0,0,0,0,0,0};
#pragma unroll
    for (int r = 0; r < 8; r++) {
        float2 d01 = __half22float2(*(__half2*)&dv[r].x);
        float2 d23 = __half22float2(*(__half2*)&dv[r].y);
        float2 d45 = __half22float2(*(__half2*)&dv[r].z);
        float2 d67 = __half22float2(*(__half2*)&dv[r].w);
        float dd[8] = {d01.x, d01.y, d23.x, d23.y, d45.x, d45.y, d67.x, d67.y};
        float ra = 0.0f;
#pragma unroll
        for (int q = 0; q < 8; q++) {
            float qq = rcp1p(ex2f(fmaf(a2[r], s0p[q], -dd[q])));
            ra = fmaf(qq, s0c[q], ra);
            colsum[q] = fmaf(qq, m[r], colsum[q]);
        }
        ra += __shfl_down_sync(~0u, ra, 16);
        ra += __shfl_down_sync(~0u, ra, 8);
        ra += __shfl_down_sync(~0u, ra, 4);
        ra += __shfl_down_sync(~0u, ra, 2);
        ra += __shfl_down_sync(~0u, ra, 1);
        if (ci == 0) g_AP[wp][cg][rBase + r] = ra;
    }

    __shared__ float sh[8][256];
#pragma unroll
    for (int q = 0; q < 8; q++) sh[rs][ci * 8 + q] = colsum[q];
    __syncthreads();
    float v = 0.0f;
#pragma unroll
    for (int s = 0; s < 8; s++) v += sh[s][tid];
    g_BvP[wp][rg][cg * 256 + tid] = v;
}

// ---------------- final: F outputs + fused A^4/Bv^4 reduction + S/C -----------
// out floats: [S: 8192][C: 8192][F: 16777216]; s1^4=g_tab[4], s1^3=g_tab[3]
// iter4 wrote partials parity 0.
__global__ void __launch_bounds__(256) final_kernel(
    const float* __restrict__ S, const float* __restrict__ C,
    const float* __restrict__ F, const float* __restrict__ W,
    float* __restrict__ out)
{
    const int row = blockIdx.x;
    const int b = row >> 11;
    const int tid = threadIdx.x;
    const float w0 = W[0], w1 = W[1];
    const float a = w1 * g_tab[4][row];
    const float4* Fr = (const float4*)F + (size_t)row * 1024;
    float4* Or = (float4*)out + 4096 + (size_t)row * 1024;
    const float* s1col = &g_tab[4][b * NN];

    float4 f[4]; float2 s[4];
#pragma unroll
    for (int u = 0; u < 4; u++) {
        int i = tid + 256 * u;
        f[u] = __ldcs(&Fr[i]);
        s[u] = *(const float2*)&s1col[2 * i];
    }
#pragma unroll
    for (int u = 0; u < 4; u++) {
        int i = tid + 256 * u;
        f[u].x = fmaf(a, 1.0f - s[u].x, f[u].x);
        f[u].z = fmaf(a, 1.0f - s[u].y, f[u].z);
        Or[i] = f[u];
    }
    if (row < 16) {
        const int i = row * 256 + tid;
        const int bb = i >> 11, c = i & (NN - 1);
        float bv = 0.0f;
#pragma unroll
        for (int t = 0; t < 32; t++) bv += g_BvP[0][bb * 32 + t][c];
        float Av = 0.0f;
#pragma unroll
        for (int g = 0; g < CGS; g++) Av += g_AP[0][g][i];

        float s13 = g_tab[3][i], s14 = g_tab[4][i];
        float Cd = C[2 * i] - C[2 * i + 1];
        float c04 = sigmoid_safe(Cd - w0 * s13);
        out[2 * i]     = S[2 * i] + w0 * c04 + w1 * Av;
        out[2 * i + 1] = S[2 * i + 1] + w1 * bv;
        out[8192 + 2 * i]     = C[2 * i];
        out[8192 + 2 * i + 1] = C[2 * i + 1] + w0 * s14;
    }
}

extern "C" void kernel_launch(void* const* d_in, const int* in_sizes, int n_in,
                              void* d_out, int out_size)
{
    const float* S = (const float*)d_in[0];
    const float* C = (const float*)d_in[1];
    const float* F = (const float*)d_in[2];
    const float* W = (const float*)d_in[3];
    float* out = (float*)d_out;

    pre_kernel<<<NBLK, 256>>>(S, F);                 // d + partials^0 + tab[0]
    for (int j = 1; j <= 4; j++)
        iter_kernel<<<NBLK, 256>>>(S, C, W, j);      // s1^j recompute + partials^j
    final_kernel<<<4096, 256>>>(S, C, F, W, out);    // outputs + A^4/Bv^4 reduce
}

// round 10
// speedup vs baseline: 1.3005x; 1.0236x over previous
#include <cuda_runtime.h>
#include <cuda_fp16.h>
#include <cstdint>

#define NN     2048
#define NODES  4096
#define RGS    64                     // row-groups (64 rows each)
#define CGS    8                      // col-groups (256 cols each)
#define NBLK   (RGS * CGS)            // 512 blocks for pre/iter
#define LOG2E  1.4426950408889634f

// ---------------- device scratch ----------------
__device__ __align__(16) __half g_nd[(size_t)NODES * NN]; // (F0-F1)*log2e fp16 (NEGATED)
__device__ __align__(16) float  g_tab[5][NODES];          // s1^0..s1^4 tables
__device__ __align__(16) float  g_AP[2][CGS][NODES];      // A partials, parity-buffered
__device__ __align__(16) float  g_BvP[2][RGS][NN];        // Bv partials, parity-buffered

__device__ __forceinline__ float ex2f(float x) {
    float r; asm("ex2.approx.f32 %0, %1;" : "=f"(r) : "f"(x)); return r;
}
__device__ __forceinline__ float frcp(float x) {
    float r; asm("rcp.approx.f32 %0, %1;" : "=f"(r) : "f"(x)); return r;
}
// accurate-path sigmoid for node updates / tables (fp32, rcp.approx err ~1e-7)
__device__ __forceinline__ float sigmoid_safe(float z) {
    z = fminf(fmaxf(z, -30.0f), 30.0f);
    return frcp(1.0f + ex2f(-z * LOG2E));
}
__device__ __forceinline__ float sigl(float zl) {        // sigmoid given z*log2e
    return frcp(1.0f + ex2f(-zl));
}

// ---------------- pre: nd=(F0-F1)*log2e (fp16) + fused iteration 0 -----------
// block (rg, cg): rows [rg*64,+64), cols [cg*256,+256); thread: 8 rows x 8 cols
__global__ void __launch_bounds__(256) pre_kernel(
    const float* __restrict__ S, const float* __restrict__ F)
{
    const int tid = threadIdx.x;
    const int rg = blockIdx.x >> 3, cg = blockIdx.x & 7;
    const int rowBase = rg * 64;
    const int b = rowBase >> 11;
    const int ci = tid & 31, rs = tid >> 5;
    const int c8 = cg * 256 + ci * 8;
    const int gc = b * NN + c8;
    const int rBase = rowBase + rs * 8;

    float s0c[8], m[8];
#pragma unroll
    for (int j = 0; j < 8; j++)
        s0c[j] = 1.0f - sigmoid_safe(S[2 * (gc + j) + 1] - S[2 * (gc + j)]);
#pragma unroll
    for (int r = 0; r < 8; r++) {
        int row = rBase + r;
        m[r] = sigmoid_safe(S[2 * row + 1] - S[2 * row]);
    }
    if (cg == 0 && tid < 64) {                   // materialize s1^0 table
        int i2 = rowBase + tid;
        g_tab[0][i2] = sigmoid_safe(S[2 * i2 + 1] - S[2 * i2]);
    }

    float colsum[8] = {0,0,0,0,0,0,0,0};
    const float4* F4 = (const float4*)F;

#pragma unroll 2
    for (int r = 0; r < 8; r++) {
        const size_t row = rBase + r;
        const size_t fo = row * 1024 + (c8 >> 1);
        float4 f0 = __ldcs(&F4[fo + 0]);
        float4 f1 = __ldcs(&F4[fo + 1]);
        float4 f2 = __ldcs(&F4[fo + 2]);
        float4 f3 = __ldcs(&F4[fo + 3]);
        float zl[8];                             // (F1-F0)*log2e
        zl[0] = (f0.y - f0.x) * LOG2E; zl[1] = (f0.w - f0.z) * LOG2E;
        zl[2] = (f1.y - f1.x) * LOG2E; zl[3] = (f1.w - f1.z) * LOG2E;
        zl[4] = (f2.y - f2.x) * LOG2E; zl[5] = (f2.w - f2.z) * LOG2E;
        zl[6] = (f3.y - f3.x) * LOG2E; zl[7] = (f3.w - f3.z) * LOG2E;

        __half2 h0 = __floats2half2_rn(-zl[0], -zl[1]);  // store NEGATED
        __half2 h1 = __floats2half2_rn(-zl[2], -zl[3]);
        __half2 h2 = __floats2half2_rn(-zl[4], -zl[5]);
        __half2 h3 = __floats2half2_rn(-zl[6], -zl[7]);
        uint4 st;
        st.x = *(unsigned*)&h0; st.y = *(unsigned*)&h1;
        st.z = *(unsigned*)&h2; st.w = *(unsigned*)&h3;
        *(uint4*)&g_nd[row * NN + c8] = st;

        float ra = 0.0f;
#pragma unroll
        for (int j = 0; j < 8; j++) {
            float q = sigl(zl[j]);
            ra = fmaf(q, s0c[j], ra);
            colsum[j] = fmaf(q, m[r], colsum[j]);
        }
        ra += __shfl_down_sync(~0u, ra, 16);
        ra += __shfl_down_sync(~0u, ra, 8);
        ra += __shfl_down_sync(~0u, ra, 4);
        ra += __shfl_down_sync(~0u, ra, 2);
        ra += __shfl_down_sync(~0u, ra, 1);
        if (ci == 0) g_AP[0][cg][row] = ra;
    }

    __shared__ float sh[8][256];
#pragma unroll
    for (int j = 0; j < 8; j++) sh[rs][ci * 8 + j] = colsum[j];
    __syncthreads();
    float v = 0.0f;
#pragma unroll
    for (int s = 0; s < 8; s++) v += sh[s][tid];
    g_BvP[0][rg][cg * 256 + tid] = v;
}

// ---------------- iter j=1..4: fused node recompute + half2 matvec ------------
__global__ void __launch_bounds__(256) iter_kernel(
    const float* __restrict__ S, const float* __restrict__ C,
    const float* __restrict__ W, int j)
{
    const int tid = threadIdx.x;
    const int rg = blockIdx.x >> 3, cg = blockIdx.x & 7;
    const int rowBase = rg * 64;
    const int b = rowBase >> 11;
    const int ci = tid & 31, rs = tid >> 5;
    const int c8 = cg * 256 + ci * 8;
    const int gc = b * NN + c8;
    const int rBase = rowBase + rs * 8;
    const int rp = (j - 1) & 1, wp = j & 1;
    const int jm2 = (j >= 2) ? j - 2 : 0;
    const float w0 = W[0], w1 = W[1];
    const float w1l = w1 * LOG2E;

    // ---- redundant node update: s1^j for my 256 cols + 64 rows ----
    __shared__ float smc[256], smr[64];
    {
        const int i = b * NN + cg * 256 + tid;
        float bv = 0.0f;
#pragma unroll
        for (int t = 0; t < 32; t++) bv += g_BvP[rp][b * 32 + t][cg * 256 + tid];
        float Av = 0.0f;
#pragma unroll
        for (int g = 0; g < CGS; g++) Av += g_AP[rp][g][i];
        float Sd = S[2 * i + 1] - S[2 * i];
        float Cd = C[2 * i] - C[2 * i + 1];
        float c0 = (j == 1) ? sigmoid_safe(Cd)
                            : sigmoid_safe(Cd - w0 * g_tab[jm2][i]);
        smc[tid] = sigmoid_safe(Sd + w1 * bv - w0 * c0 - w1 * Av);
    }
    if (tid < 64) {
        const int i2 = rowBase + tid;
        const int c2 = i2 & (NN - 1);
        float bv = 0.0f;
#pragma unroll
        for (int t = 0; t < 32; t++) bv += g_BvP[rp][b * 32 + t][c2];
        float Av = 0.0f;
#pragma unroll
        for (int g = 0; g < CGS; g++) Av += g_AP[rp][g][i2];
        float Sd = S[2 * i2 + 1] - S[2 * i2];
        float Cd = C[2 * i2] - C[2 * i2 + 1];
        float c0 = (j == 1) ? sigmoid_safe(Cd)
                            : sigmoid_safe(Cd - w0 * g_tab[jm2][i2]);
        float vv = sigmoid_safe(Sd + w1 * bv - w0 * c0 - w1 * Av);
        smr[tid] = vv;
        if (cg == 0) g_tab[j][i2] = vv;
    }
    __syncthreads();

    // ---- mainloop (half2) ----
    float s0c[8], m[8];
#pragma unroll
    for (int q = 0; q < 8; q++) s0c[q] = 1.0f - smc[ci * 8 + q];
    __half2 s0ph[4];
    {
        float4 p0 = *(const float4*)&g_tab[j - 1][gc];
        float4 p1 = *(const float4*)&g_tab[j - 1][gc + 4];
        s0ph[0] = __floats2half2_rn(1.f - p0.x, 1.f - p0.y);
        s0ph[1] = __floats2half2_rn(1.f - p0.z, 1.f - p0.w);
        s0ph[2] = __floats2half2_rn(1.f - p1.x, 1.f - p1.y);
        s0ph[3] = __floats2half2_rn(1.f - p1.z, 1.f - p1.w);
    }
    float a2[8];
#pragma unroll
    for (int r = 0; r < 8; r++) {
        a2[r] = w1l * g_tab[j - 1][rBase + r];
        m[r]  = smr[rs * 8 + r];
    }

    uint4 dv[8];
    const __half* dp = g_nd + (size_t)rBase * NN + c8;
#pragma unroll
    for (int r = 0; r < 8; r++)
        dv[r] = *(const uint4*)(dp + (size_t)r * NN);

    float colsum[8] = {0,0,0,0,0,0,0,0};
#pragma unroll
    for (int r = 0; r < 8; r++) {
        const __half2 a2h = __float2half2_rn(a2[r]);
        const __half2* nd2 = (const __half2*)&dv[r];
        float ra = 0.0f;
#pragma unroll
        for (int jj = 0; jj < 4; jj++) {
            // z2 = a2*s0p + (F0-F1)*log2e ; q = 1/(1+2^z2)
            __half2 z2 = __hfma2(a2h, s0ph[jj], nd2[jj]);
            __half2 e2 = h2exp2(z2);
            float2 ef = __half22float2(e2);
            float q0 = frcp(1.0f + ef.x);
            float q1 = frcp(1.0f + ef.y);
            ra = fmaf(q0, s0c[2 * jj], ra);
            ra = fmaf(q1, s0c[2 * jj + 1], ra);
            colsum[2 * jj]     = fmaf(q0, m[r], colsum[2 * jj]);
            colsum[2 * jj + 1] = fmaf(q1, m[r], colsum[2 * jj + 1]);
        }
        ra += __shfl_down_sync(~0u, ra, 16);
        ra += __shfl_down_sync(~0u, ra, 8);
        ra += __shfl_down_sync(~0u, ra, 4);
        ra += __shfl_down_sync(~0u, ra, 2);
        ra += __shfl_down_sync(~0u, ra, 1);
        if (ci == 0) g_AP[wp][cg][rBase + r] = ra;
    }

    __shared__ float sh[8][256];
#pragma unroll
    for (int q = 0; q < 8; q++) sh[rs][ci * 8 + q] = colsum[q];
    __syncthreads();
    float v = 0.0f;
#pragma unroll
    for (int s = 0; s < 8; s++) v += sh[s][tid];
    g_BvP[wp][rg][cg * 256 + tid] = v;
}

// ---------------- final: F outputs + fused A^4/Bv^4 reduction + S/C -----------
// out floats: [S: 8192][C: 8192][F: 16777216]; s1^4=g_tab[4], s1^3=g_tab[3]
__global__ void __launch_bounds__(256) final_kernel(
    const float* __restrict__ S, const float* __restrict__ C,
    const float* __restrict__ F, const float* __restrict__ W,
    float* __restrict__ out)
{
    const int row = blockIdx.x;
    const int b = row >> 11;
    const int tid = threadIdx.x;
    const float w0 = W[0], w1 = W[1];
    const float a = w1 * g_tab[4][row];
    const float4* Fr = (const float4*)F + (size_t)row * 1024;
    float4* Or = (float4*)out + 4096 + (size_t)row * 1024;
    const float* s1col = &g_tab[4][b * NN];

    float4 f[4]; float2 s[4];
#pragma unroll
    for (int u = 0; u < 4; u++) {
        int i = tid + 256 * u;
        f[u] = __ldcs(&Fr[i]);
        s[u] = *(const float2*)&s1col[2 * i];
    }
#pragma unroll
    for (int u = 0; u < 4; u++) {
        int i = tid + 256 * u;
        f[u].x = fmaf(a, 1.0f - s[u].x, f[u].x);
        f[u].z = fmaf(a, 1.0f - s[u].y, f[u].z);
        __stcs(&Or[i], f[u]);
    }
    if (row < 16) {
        const int i = row * 256 + tid;
        const int bb = i >> 11, c = i & (NN - 1);
        float bv = 0.0f;
#pragma unroll
        for (int t = 0; t < 32; t++) bv += g_BvP[0][bb * 32 + t][c];
        float Av = 0.0f;
#pragma unroll
        for (int g = 0; g < CGS; g++) Av += g_AP[0][g][i];

        float s13 = g_tab[3][i], s14 = g_tab[4][i];
        float Cd = C[2 * i] - C[2 * i + 1];
        float c04 = sigmoid_safe(Cd - w0 * s13);
        out[2 * i]     = S[2 * i] + w0 * c04 + w1 * Av;
        out[2 * i + 1] = S[2 * i + 1] + w1 * bv;
        out[8192 + 2 * i]     = C[2 * i];
        out[8192 + 2 * i + 1] = C[2 * i + 1] + w0 * s14;
    }
}

extern "C" void kernel_launch(void* const* d_in, const int* in_sizes, int n_in,
                              void* d_out, int out_size)
{
    const float* S = (const float*)d_in[0];
    const float* C = (const float*)d_in[1];
    const float* F = (const float*)d_in[2];
    const float* W = (const float*)d_in[3];
    float* out = (float*)d_out;

    pre_kernel<<<NBLK, 256>>>(S, F);                 // nd + partials^0 + tab[0]
    for (int j = 1; j <= 4; j++)
        iter_kernel<<<NBLK, 256>>>(S, C, W, j);      // s1^j recompute + partials^j
    final_kernel<<<4096, 256>>>(S, C, F, W, out);    // outputs + A^4/Bv^4 reduce
}

// round 11
// speedup vs baseline: 1.4009x; 1.0772x over previous
#include <cuda_runtime.h>
#include <cuda_fp16.h>
#include <cstdint>

#define NN     2048
#define NODES  4096
#define RGS    64                     // row-groups (64 rows each)
#define CGS    8                      // col-groups (256 cols each)
#define NBLK   (RGS * CGS)            // 512 blocks for pre/iter
#define LOG2E  1.4426950408889634f

// ---------------- device scratch ----------------
__device__ __align__(16) __half g_hd[(size_t)NODES * NN]; // (F1-F0)/2 fp16, 16.8MB
__device__ __align__(16) float  g_tab[5][NODES];          // s1^0..s1^4 tables
__device__ __align__(16) float  g_AP[2][CGS][NODES];      // A partials, parity-buffered
__device__ __align__(16) float  g_BvP[2][RGS][NN];        // Bv partials, parity-buffered

__device__ __forceinline__ float ex2f(float x) {
    float r; asm("ex2.approx.f32 %0, %1;" : "=f"(r) : "f"(x)); return r;
}
__device__ __forceinline__ float frcp(float x) {
    float r; asm("rcp.approx.f32 %0, %1;" : "=f"(r) : "f"(x)); return r;
}
__device__ __forceinline__ __half2 tanh2(__half2 x) {     // native MUFU.TANH f16x2
    __half2 r;
    asm("tanh.approx.f16x2 %0, %1;"
        : "=r"(*(unsigned*)&r) : "r"(*(unsigned*)&x));
    return r;
}
// accurate-path sigmoid for node updates / tables
__device__ __forceinline__ float sigmoid_safe(float z) {
    z = fminf(fmaxf(z, -30.0f), 30.0f);
    return frcp(1.0f + ex2f(-z * LOG2E));
}
__device__ __forceinline__ float sigl(float zl) { return frcp(1.0f + ex2f(-zl)); }

// ---------------- pre: hd=(F1-F0)/2 (fp16) + fused iteration 0 ---------------
// block (rg, cg): rows [rg*64,+64), cols [cg*256,+256); thread: 8 rows x 8 cols
__global__ void __launch_bounds__(256) pre_kernel(
    const float* __restrict__ S, const float* __restrict__ F)
{
    const int tid = threadIdx.x;
    const int rg = blockIdx.x >> 3, cg = blockIdx.x & 7;
    const int rowBase = rg * 64;
    const int b = rowBase >> 11;
    const int ci = tid & 31, rs = tid >> 5;
    const int c8 = cg * 256 + ci * 8;
    const int gc = b * NN + c8;
    const int rBase = rowBase + rs * 8;

    float s0c[8], m[8];
#pragma unroll
    for (int j = 0; j < 8; j++)
        s0c[j] = 1.0f - sigmoid_safe(S[2 * (gc + j) + 1] - S[2 * (gc + j)]);
#pragma unroll
    for (int r = 0; r < 8; r++) {
        int row = rBase + r;
        m[r] = sigmoid_safe(S[2 * row + 1] - S[2 * row]);
    }
    if (cg == 0 && tid < 64) {                   // materialize s1^0 table
        int i2 = rowBase + tid;
        g_tab[0][i2] = sigmoid_safe(S[2 * i2 + 1] - S[2 * i2]);
    }

    float colsum[8] = {0,0,0,0,0,0,0,0};
    const float4* F4 = (const float4*)F;

#pragma unroll 2
    for (int r = 0; r < 8; r++) {
        const size_t row = rBase + r;
        const size_t fo = row * 1024 + (c8 >> 1);
        float4 f0 = __ldcs(&F4[fo + 0]);
        float4 f1 = __ldcs(&F4[fo + 1]);
        float4 f2 = __ldcs(&F4[fo + 2]);
        float4 f3 = __ldcs(&F4[fo + 3]);
        float dd[8];
        dd[0] = f0.y - f0.x; dd[1] = f0.w - f0.z;
        dd[2] = f1.y - f1.x; dd[3] = f1.w - f1.z;
        dd[4] = f2.y - f2.x; dd[5] = f2.w - f2.z;
        dd[6] = f3.y - f3.x; dd[7] = f3.w - f3.z;

        __half2 h0 = __floats2half2_rn(dd[0] * 0.5f, dd[1] * 0.5f);
        __half2 h1 = __floats2half2_rn(dd[2] * 0.5f, dd[3] * 0.5f);
        __half2 h2 = __floats2half2_rn(dd[4] * 0.5f, dd[5] * 0.5f);
        __half2 h3 = __floats2half2_rn(dd[6] * 0.5f, dd[7] * 0.5f);
        uint4 st;
        st.x = *(unsigned*)&h0; st.y = *(unsigned*)&h1;
        st.z = *(unsigned*)&h2; st.w = *(unsigned*)&h3;
        *(uint4*)&g_hd[row * NN + c8] = st;

        float ra = 0.0f;
#pragma unroll
        for (int j = 0; j < 8; j++) {
            float q = sigl(dd[j] * LOG2E);
            ra = fmaf(q, s0c[j], ra);
            colsum[j] = fmaf(q, m[r], colsum[j]);
        }
        ra += __shfl_down_sync(~0u, ra, 16);
        ra += __shfl_down_sync(~0u, ra, 8);
        ra += __shfl_down_sync(~0u, ra, 4);
        ra += __shfl_down_sync(~0u, ra, 2);
        ra += __shfl_down_sync(~0u, ra, 1);
        if (ci == 0) g_AP[0][cg][row] = ra;
    }

    __shared__ float sh[8][256];
#pragma unroll
    for (int j = 0; j < 8; j++) sh[rs][ci * 8 + j] = colsum[j];
    __syncthreads();
    float v = 0.0f;
#pragma unroll
    for (int s = 0; s < 8; s++) v += sh[s][tid];
    g_BvP[0][rg][cg * 256 + tid] = v;
}

// ---------------- iter j=1..4: fused node recompute + tanh f16x2 matvec -------
__global__ void __launch_bounds__(256) iter_kernel(
    const float* __restrict__ S, const float* __restrict__ C,
    const float* __restrict__ W, int j)
{
    const int tid = threadIdx.x;
    const int rg = blockIdx.x >> 3, cg = blockIdx.x & 7;
    const int rowBase = rg * 64;
    const int b = rowBase >> 11;
    const int ci = tid & 31, rs = tid >> 5;
    const int c8 = cg * 256 + ci * 8;
    const int gc = b * NN + c8;
    const int rBase = rowBase + rs * 8;
    const int rp = (j - 1) & 1, wp = j & 1;
    const int jm2 = (j >= 2) ? j - 2 : 0;
    const float w0 = W[0], w1 = W[1];

    // ---- redundant node update: s1^j for my 256 cols + 64 rows ----
    __shared__ float smc[256], smr[64];
    {
        const int i = b * NN + cg * 256 + tid;
        float bv = 0.0f;
#pragma unroll
        for (int t = 0; t < 32; t++) bv += g_BvP[rp][b * 32 + t][cg * 256 + tid];
        float Av = 0.0f;
#pragma unroll
        for (int g = 0; g < CGS; g++) Av += g_AP[rp][g][i];
        float Sd = S[2 * i + 1] - S[2 * i];
        float Cd = C[2 * i] - C[2 * i + 1];
        float c0 = (j == 1) ? sigmoid_safe(Cd)
                            : sigmoid_safe(Cd - w0 * g_tab[jm2][i]);
        smc[tid] = sigmoid_safe(Sd + w1 * bv - w0 * c0 - w1 * Av);
    }
    if (tid < 64) {
        const int i2 = rowBase + tid;
        const int c2 = i2 & (NN - 1);
        float bv = 0.0f;
#pragma unroll
        for (int t = 0; t < 32; t++) bv += g_BvP[rp][b * 32 + t][c2];
        float Av = 0.0f;
#pragma unroll
        for (int g = 0; g < CGS; g++) Av += g_AP[rp][g][i2];
        float Sd = S[2 * i2 + 1] - S[2 * i2];
        float Cd = C[2 * i2] - C[2 * i2 + 1];
        float c0 = (j == 1) ? sigmoid_safe(Cd)
                            : sigmoid_safe(Cd - w0 * g_tab[jm2][i2]);
        float vv = sigmoid_safe(Sd + w1 * bv - w0 * c0 - w1 * Av);
        smr[tid] = vv;
        if (cg == 0) g_tab[j][i2] = vv;
    }
    __syncthreads();

    // ---- mainloop: q = 0.5 + 0.5*tanh(hd - (w1*s1p/2)*s0p) ----
    float s0c[8], m[8];
#pragma unroll
    for (int q = 0; q < 8; q++) s0c[q] = 1.0f - smc[ci * 8 + q];
    float s0csum = ((s0c[0] + s0c[1]) + (s0c[2] + s0c[3])) +
                   ((s0c[4] + s0c[5]) + (s0c[6] + s0c[7]));
    __half2 s0ph[4];
    {
        float4 p0 = *(const float4*)&g_tab[j - 1][gc];
        float4 p1 = *(const float4*)&g_tab[j - 1][gc + 4];
        s0ph[0] = __floats2half2_rn(1.f - p0.x, 1.f - p0.y);
        s0ph[1] = __floats2half2_rn(1.f - p0.z, 1.f - p0.w);
        s0ph[2] = __floats2half2_rn(1.f - p1.x, 1.f - p1.y);
        s0ph[3] = __floats2half2_rn(1.f - p1.z, 1.f - p1.w);
    }
    float a2[8];
#pragma unroll
    for (int r = 0; r < 8; r++) {
        a2[r] = -0.5f * w1 * g_tab[j - 1][rBase + r];   // negated half-scale
        m[r]  = smr[rs * 8 + r];
    }
    float msum = ((m[0] + m[1]) + (m[2] + m[3])) + ((m[4] + m[5]) + (m[6] + m[7]));

    uint4 dv[8];
    const __half* dp = g_hd + (size_t)rBase * NN + c8;
#pragma unroll
    for (int r = 0; r < 8; r++)
        dv[r] = *(const uint4*)(dp + (size_t)r * NN);

    float colsum[8] = {0,0,0,0,0,0,0,0};    // accumulates sum of t*m
#pragma unroll
    for (int r = 0; r < 8; r++) {
        const __half2 a2h = __float2half2_rn(a2[r]);
        const __half2* hd2 = (const __half2*)&dv[r];
        float ra = 0.0f;                    // accumulates sum of t*s0c
#pragma unroll
        for (int jj = 0; jj < 4; jj++) {
            __half2 z2 = __hfma2(a2h, s0ph[jj], hd2[jj]);
            float2 tf = __half22float2(tanh2(z2));
            ra = fmaf(tf.x, s0c[2 * jj], ra);
            ra = fmaf(tf.y, s0c[2 * jj + 1], ra);
            colsum[2 * jj]     = fmaf(tf.x, m[r], colsum[2 * jj]);
            colsum[2 * jj + 1] = fmaf(tf.y, m[r], colsum[2 * jj + 1]);
        }
        ra = 0.5f * (s0csum + ra);          // fold q = 0.5 + 0.5*t
        ra += __shfl_down_sync(~0u, ra, 16);
        ra += __shfl_down_sync(~0u, ra, 8);
        ra += __shfl_down_sync(~0u, ra, 4);
        ra += __shfl_down_sync(~0u, ra, 2);
        ra += __shfl_down_sync(~0u, ra, 1);
        if (ci == 0) g_AP[wp][cg][rBase + r] = ra;
    }

    __shared__ float sh[8][256];
#pragma unroll
    for (int q = 0; q < 8; q++) sh[rs][ci * 8 + q] = 0.5f * (msum + colsum[q]);
    __syncthreads();
    float v = 0.0f;
#pragma unroll
    for (int s = 0; s < 8; s++) v += sh[s][tid];
    g_BvP[wp][rg][cg * 256 + tid] = v;
}

// ---------------- final: F outputs + fused A^4/Bv^4 reduction + S/C -----------
// out floats: [S: 8192][C: 8192][F: 16777216]; s1^4=g_tab[4], s1^3=g_tab[3]
__global__ void __launch_bounds__(256) final_kernel(
    const float* __restrict__ S, const float* __restrict__ C,
    const float* __restrict__ F, const float* __restrict__ W,
    float* __restrict__ out)
{
    const int row = blockIdx.x;
    const int b = row >> 11;
    const int tid = threadIdx.x;
    const float w0 = W[0], w1 = W[1];
    const float a = w1 * g_tab[4][row];
    const float4* Fr = (const float4*)F + (size_t)row * 1024;
    float4* Or = (float4*)out + 4096 + (size_t)row * 1024;
    const float* s1col = &g_tab[4][b * NN];

    float4 f[4]; float2 s[4];
#pragma unroll
    for (int u = 0; u < 4; u++) {
        int i = tid + 256 * u;
        f[u] = __ldcs(&Fr[i]);
        s[u] = *(const float2*)&s1col[2 * i];
    }
#pragma unroll
    for (int u = 0; u < 4; u++) {
        int i = tid + 256 * u;
        f[u].x = fmaf(a, 1.0f - s[u].x, f[u].x);
        f[u].z = fmaf(a, 1.0f - s[u].y, f[u].z);
        __stcs(&Or[i], f[u]);
    }
    if (row < 16) {
        const int i = row * 256 + tid;
        const int bb = i >> 11, c = i & (NN - 1);
        float bv = 0.0f;
#pragma unroll
        for (int t = 0; t < 32; t++) bv += g_BvP[0][bb * 32 + t][c];
        float Av = 0.0f;
#pragma unroll
        for (int g = 0; g < CGS; g++) Av += g_AP[0][g][i];

        float s13 = g_tab[3][i], s14 = g_tab[4][i];
        float Cd = C[2 * i] - C[2 * i + 1];
        float c04 = sigmoid_safe(Cd - w0 * s13);
        out[2 * i]     = S[2 * i] + w0 * c04 + w1 * Av;
        out[2 * i + 1] = S[2 * i + 1] + w1 * bv;
        out[8192 + 2 * i]     = C[2 * i];
        out[8192 + 2 * i + 1] = C[2 * i + 1] + w0 * s14;
    }
}

extern "C" void kernel_launch(void* const* d_in, const int* in_sizes, int n_in,
                              void* d_out, int out_size)
{
    const float* S = (const float*)d_in[0];
    const float* C = (const float*)d_in[1];
    const float* F = (const float*)d_in[2];
    const float* W = (const float*)d_in[3];
    float* out = (float*)d_out;

    pre_kernel<<<NBLK, 256>>>(S, F);                 // hd + partials^0 + tab[0]
    for (int j = 1; j <= 4; j++)
        iter_kernel<<<NBLK, 256>>>(S, C, W, j);      // s1^j recompute + partials^j
    final_kernel<<<4096, 256>>>(S, C, F, W, out);    // outputs + A^4/Bv^4 reduce
}